// round 15
// baseline (speedup 1.0000x reference)
#include <cuda_runtime.h>
#include <cuda_fp16.h>
#include <cstdint>

#define NBLOCKS 6250
#define ACHUNK_BYTES (128 * 128)            // 128 rows x 64 fp16 cols
#define SMEM_BYTES (4 * ACHUNK_BYTES + 1024)

// fp16 B fragments for mma.m16n8k16, 4 N-groups of 32 cols (R12/R13-proven):
// g_Bf16[(((wn4*16 + ks)*32 + lane)*8) + nt*2 + j]
//   = half2(W[wn4*32+nt*8+g][ks*16+2t+8j], W[...][...+1])
__device__ uint32_t g_Bf16[16384];          // 64 KB, L1/L2-resident

__global__ void prep_b16(const float* __restrict__ W) {
    int i = blockIdx.x * 256 + threadIdx.x;   // 0..16383
    int wn4  = i >> 12;          // 0..3
    int ks   = (i >> 8) & 15;    // 0..15
    int lane = (i >> 3) & 31;
    int idx  = i & 7;
    int nt = idx >> 1, j = idx & 1;
    int g = lane >> 2, t = lane & 3;
    int n = wn4 * 32 + nt * 8 + g;
    int k = ks * 16 + 2 * t + 8 * j;
    __half2 h = __floats2half2_rn(W[n * 256 + k], W[n * 256 + k + 1]);
    g_Bf16[i] = *(uint32_t*)&h;
}

__device__ __forceinline__ uint32_t smem_u32(const void* p) {
    uint32_t a;
    asm("{ .reg .u64 t; cvta.to.shared.u64 t, %1; cvt.u32.u64 %0, t; }" : "=r"(a) : "l"(p));
    return a;
}
__device__ __forceinline__ uint32_t pack_h2(float x, float y) {
    __half2 h = __floats2half2_rn(x, y);
    return *(uint32_t*)&h;
}
__device__ __forceinline__ void ldsm4(uint32_t& a0, uint32_t& a1, uint32_t& a2,
                                      uint32_t& a3, uint32_t addr) {
    asm volatile("ldmatrix.sync.aligned.m8n8.x4.shared.b16 {%0,%1,%2,%3}, [%4];"
                 : "=r"(a0), "=r"(a1), "=r"(a2), "=r"(a3) : "r"(addr));
}
__device__ __forceinline__ void mma16(float* acc, uint32_t a0, uint32_t a1,
                                      uint32_t a2, uint32_t a3,
                                      uint32_t b0, uint32_t b1) {
    asm volatile(
        "mma.sync.aligned.m16n8k16.row.col.f32.f16.f16.f32 "
        "{%0,%1,%2,%3}, {%4,%5,%6,%7}, {%8,%9}, {%0,%1,%2,%3};\n"
        : "+f"(acc[0]), "+f"(acc[1]), "+f"(acc[2]), "+f"(acc[3])
        : "r"(a0), "r"(a1), "r"(a2), "r"(a3), "r"(b0), "r"(b1));
}

// CTA: 128 edges x 128 outputs. 256 threads = 8 warps (2M x 4N), warp tile 64x32.
// Overlapped schedule: stage H chunks -> bar -> compute ks0-3 | sts2+ldg3 |
// compute ks4-7 | sts3 -> bar -> compute ks8-15. E-chunk LDG hidden under mma.
__global__ void __launch_bounds__(256, 2) msg_mma_kernel(
    const float* __restrict__ H,
    const float* __restrict__ E,
    const int*   __restrict__ heads,
    const float* __restrict__ bias,
    float*       __restrict__ out)
{
    extern __shared__ __align__(1024) char smem[];
    float* bias_s  = (float*)(smem + 4 * ACHUNK_BYTES);
    int*   heads_s = (int*)(bias_s + 128);
    const uint32_t sbase = smem_u32(smem);

    const int tid  = threadIdx.x;
    const int warp = tid >> 5;
    const int lane = tid & 31;
    const int warp_m = warp >> 2;        // 0..1 -> rows warp_m*64
    const int warp_n = warp & 3;         // 0..3 -> cols warp_n*32
    const int g = lane >> 2;
    const int t = lane & 3;
    const int block_m = blockIdx.x * 128;

    if (tid < 128) {
        bias_s[tid]  = bias[tid];
        heads_s[tid] = heads[block_m + tid];
    }
    __syncthreads();

    // ---- A-load lane mapping: 16 lanes cover one row's 64-float chunk ----
    const int lane_lo = lane & 15;
    const int half    = lane >> 4;
    const int rbase   = warp * 16 + half;   // rows rbase + 2*o, o = 0..7

    uint2 stg[8];
    auto ldg_chunk = [&](int c) {
        const int coff = (c & 1) * 64 + lane_lo * 4;
        #pragma unroll
        for (int o = 0; o < 8; o++) {
            const int row = rbase + o * 2;
            float4 v;
            if (c < 2) {
                v = *(const float4*)(H + (size_t)heads_s[row] * 128 + coff);
            } else {
                v = __ldcs((const float4*)(E + (size_t)(block_m + row) * 128 + coff));
            }
            stg[o] = make_uint2(pack_h2(v.x, v.y), pack_h2(v.z, v.w));
        }
    };
    auto sts_chunk = [&](int c) {
        const uint32_t off = (uint32_t)(c * ACHUNK_BYTES);
        #pragma unroll
        for (int o = 0; o < 8; o++) {
            const int row = rbase + o * 2;
            uint32_t b = (uint32_t)(row * 128 + lane_lo * 8);
            b ^= (uint32_t)((row & 7) << 4);
            *(uint2*)(smem + off + b) = stg[o];
        }
    };

    // ---- ldmatrix lane bases per mt: UNSWIZZLED; XOR mask applied at use ----
    const int row_sel = (lane & 7) + ((lane >> 3) & 1) * 8;
    const int kb2     = ((lane >> 4) & 1) * 16;
    const uint32_t xmask = (uint32_t)((lane & 7) << 4);
    uint32_t lm[4];
    #pragma unroll
    for (int mt = 0; mt < 4; mt++) {
        const int row0 = warp_m * 64 + mt * 16;
        lm[mt] = sbase + (uint32_t)((row0 + row_sel) * 128 + kb2);
    }

    float acc[4][4][4];                     // 64 regs
    #pragma unroll
    for (int mt = 0; mt < 4; mt++)
        #pragma unroll
        for (int nt = 0; nt < 4; nt++)
            #pragma unroll
            for (int i = 0; i < 4; i++) acc[mt][nt][i] = 0.0f;

    const uint4* bbase = (const uint4*)g_Bf16 + (warp_n * 16 * 32 + lane) * 2;

    // compute k-steps [k0, k1), B reg double-buffered
    auto compute = [&](int k0, int k1) {
        uint4 qa[2], qb[2];
        {
            const uint4* bp = bbase + (size_t)k0 * 32 * 2;
            qa[0] = bp[0]; qa[1] = bp[1];
        }
        #pragma unroll
        for (int ks = k0; ks < k1; ks++) {
            const uint4* cur = ((ks - k0) & 1) ? qb : qa;
            uint4* nxt = ((ks - k0) & 1) ? qa : qb;
            if (ks + 1 < k1) {
                const uint4* bp = bbase + (size_t)(ks + 1) * 32 * 2;
                nxt[0] = bp[0]; nxt[1] = bp[1];
            }
            uint32_t bf[4][2] = {
                {cur[0].x, cur[0].y}, {cur[0].z, cur[0].w},
                {cur[1].x, cur[1].y}, {cur[1].z, cur[1].w}};
            const uint32_t aoff = (uint32_t)((ks >> 2) * ACHUNK_BYTES + (ks & 3) * 32);
            #pragma unroll
            for (int mt = 0; mt < 4; mt++) {
                uint32_t a0, a1, a2, a3;
                ldsm4(a0, a1, a2, a3, (lm[mt] + aoff) ^ xmask);
                #pragma unroll
                for (int nt = 0; nt < 4; nt++)
                    mma16(acc[mt][nt], a0, a1, a2, a3, bf[nt][0], bf[nt][1]);
            }
        }
    };

    // ---- overlapped schedule ----
    ldg_chunk(0); sts_chunk(0);
    ldg_chunk(1); sts_chunk(1);
    ldg_chunk(2);                 // E chunk 2 LDG in flight across barrier
    __syncthreads();
    compute(0, 4);                // chunk 0
    sts_chunk(2);
    ldg_chunk(3);                 // E chunk 3 LDG hidden under chunk-1 compute
    compute(4, 8);                // chunk 1
    sts_chunk(3);
    __syncthreads();
    compute(8, 16);               // chunks 2,3

    // ---- Epilogue (R13-proven): +bias, streaming float2 stores ----
    #pragma unroll
    for (int mt = 0; mt < 4; mt++) {
        const int row0 = block_m + warp_m * 64 + mt * 16 + g;
        #pragma unroll
        for (int nt = 0; nt < 4; nt++) {
            const int col = warp_n * 32 + nt * 8 + t * 2;
            float2 bv = *(const float2*)(bias_s + col);
            float2 v0, v1;
            v0.x = acc[mt][nt][0] + bv.x;
            v0.y = acc[mt][nt][1] + bv.y;
            v1.x = acc[mt][nt][2] + bv.x;
            v1.y = acc[mt][nt][3] + bv.y;
            __stcs((float2*)(out + (size_t)row0 * 128 + col), v0);
            __stcs((float2*)(out + (size_t)(row0 + 8) * 128 + col), v1);
        }
    }
}

extern "C" void kernel_launch(void* const* d_in, const int* in_sizes, int n_in,
                              void* d_out, int out_size) {
    const float* H     = (const float*)d_in[0];
    const float* E     = (const float*)d_in[1];
    const int*   heads = (const int*)d_in[2];
    // d_in[3] = queries (unused)
    const float* W     = (const float*)d_in[4];
    const float* b     = (const float*)d_in[5];
    float* out = (float*)d_out;

    cudaFuncSetAttribute(msg_mma_kernel,
                         cudaFuncAttributeMaxDynamicSharedMemorySize, SMEM_BYTES);

    prep_b16<<<64, 256>>>(W);
    msg_mma_kernel<<<NBLOCKS, 256, SMEM_BYTES>>>(H, E, heads, b, out);
}

// round 16
// speedup vs baseline: 1.1594x; 1.1594x over previous
#include <cuda_runtime.h>
#include <cuda_fp16.h>
#include <cstdint>

#define NBLOCKS 6250
#define ACHUNK_BYTES (128 * 128)            // 128 rows x 64 fp16 cols
#define SMEM_BYTES (4 * ACHUNK_BYTES + 1024)

// fp16 B fragments for mma.m16n8k16, 4 N-groups of 32 cols (R12/R13-proven):
// g_Bf16[(((wn4*16 + ks)*32 + lane)*8) + nt*2 + j]
//   = half2(W[wn4*32+nt*8+g][ks*16+2t+8j], W[...][...+1])
__device__ uint32_t g_Bf16[16384];          // 64 KB, L1/L2-resident

__global__ void prep_b16(const float* __restrict__ W) {
    int i = blockIdx.x * 256 + threadIdx.x;   // 0..16383
    int wn4  = i >> 12;          // 0..3
    int ks   = (i >> 8) & 15;    // 0..15
    int lane = (i >> 3) & 31;
    int idx  = i & 7;
    int nt = idx >> 1, j = idx & 1;
    int g = lane >> 2, t = lane & 3;
    int n = wn4 * 32 + nt * 8 + g;
    int k = ks * 16 + 2 * t + 8 * j;
    __half2 h = __floats2half2_rn(W[n * 256 + k], W[n * 256 + k + 1]);
    g_Bf16[i] = *(uint32_t*)&h;
}

__device__ __forceinline__ uint32_t smem_u32(const void* p) {
    uint32_t a;
    asm("{ .reg .u64 t; cvta.to.shared.u64 t, %1; cvt.u32.u64 %0, t; }" : "=r"(a) : "l"(p));
    return a;
}
__device__ __forceinline__ uint32_t pack_h2(float x, float y) {
    __half2 h = __floats2half2_rn(x, y);
    return *(uint32_t*)&h;
}
__device__ __forceinline__ void ldsm4(uint32_t& a0, uint32_t& a1, uint32_t& a2,
                                      uint32_t& a3, uint32_t addr) {
    asm volatile("ldmatrix.sync.aligned.m8n8.x4.shared.b16 {%0,%1,%2,%3}, [%4];"
                 : "=r"(a0), "=r"(a1), "=r"(a2), "=r"(a3) : "r"(addr));
}
__device__ __forceinline__ void mma16(float* acc, uint32_t a0, uint32_t a1,
                                      uint32_t a2, uint32_t a3,
                                      uint32_t b0, uint32_t b1) {
    asm volatile(
        "mma.sync.aligned.m16n8k16.row.col.f32.f16.f16.f32 "
        "{%0,%1,%2,%3}, {%4,%5,%6,%7}, {%8,%9}, {%0,%1,%2,%3};\n"
        : "+f"(acc[0]), "+f"(acc[1]), "+f"(acc[2]), "+f"(acc[3])
        : "r"(a0), "r"(a1), "r"(a2), "r"(a3), "r"(b0), "r"(b1));
}

// CTA: 128 edges x 128 outputs. 256 threads = 8 warps (2M x 4N), warp tile 64x32.
// WIDE PROLOGUE: 4 independent staging sets -> all 32 LDG.128/thread in flight
// (no WAR chain), then all STS, ONE barrier, unbroken 16-kstep mma stream.
__global__ void __launch_bounds__(256, 2) msg_mma_kernel(
    const float* __restrict__ H,
    const float* __restrict__ E,
    const int*   __restrict__ heads,
    const float* __restrict__ bias,
    float*       __restrict__ out)
{
    extern __shared__ __align__(1024) char smem[];
    float* bias_s  = (float*)(smem + 4 * ACHUNK_BYTES);
    int*   heads_s = (int*)(bias_s + 128);
    const uint32_t sbase = smem_u32(smem);

    const int tid  = threadIdx.x;
    const int warp = tid >> 5;
    const int lane = tid & 31;
    const int warp_m = warp >> 2;        // 0..1 -> rows warp_m*64
    const int warp_n = warp & 3;         // 0..3 -> cols warp_n*32
    const int g = lane >> 2;
    const int t = lane & 3;
    const int block_m = blockIdx.x * 128;

    if (tid < 128) {
        bias_s[tid]  = bias[tid];
        heads_s[tid] = heads[block_m + tid];
    }
    __syncthreads();

    // ---- A-load lane mapping: 16 lanes cover one row's 64-float chunk ----
    const int lane_lo = lane & 15;
    const int half    = lane >> 4;
    const int rbase   = warp * 16 + half;   // rows rbase + 2*o, o = 0..7

    // ---- WIDE PROLOGUE: 4 independent staging sets, all LDGs in flight ----
    uint2 stg0[8], stg1[8], stg2[8], stg3[8];
    {
        uint2* sets[4] = {stg0, stg1, stg2, stg3};
        #pragma unroll
        for (int c = 0; c < 4; c++) {
            const int coff = (c & 1) * 64 + lane_lo * 4;
            uint2* sg = sets[c];
            #pragma unroll
            for (int o = 0; o < 8; o++) {
                const int row = rbase + o * 2;
                float4 v;
                if (c < 2) {
                    v = *(const float4*)(H + (size_t)heads_s[row] * 128 + coff);
                } else {
                    v = __ldcs((const float4*)(E + (size_t)(block_m + row) * 128 + coff));
                }
                sg[o] = make_uint2(pack_h2(v.x, v.y), pack_h2(v.z, v.w));
            }
        }
        #pragma unroll
        for (int c = 0; c < 4; c++) {
            const uint32_t off = (uint32_t)(c * ACHUNK_BYTES);
            uint2* sg = sets[c];
            #pragma unroll
            for (int o = 0; o < 8; o++) {
                const int row = rbase + o * 2;
                uint32_t b = (uint32_t)(row * 128 + lane_lo * 8);
                b ^= (uint32_t)((row & 7) << 4);
                *(uint2*)(smem + off + b) = sg[o];
            }
        }
    }

    // ---- ldmatrix lane bases per mt: UNSWIZZLED; XOR mask applied at use ----
    const int row_sel = (lane & 7) + ((lane >> 3) & 1) * 8;
    const int kb2     = ((lane >> 4) & 1) * 16;
    const uint32_t xmask = (uint32_t)((lane & 7) << 4);
    uint32_t lm[4];
    #pragma unroll
    for (int mt = 0; mt < 4; mt++) {
        const int row0 = warp_m * 64 + mt * 16;
        lm[mt] = sbase + (uint32_t)((row0 + row_sel) * 128 + kb2);
    }

    float acc[4][4][4];                     // 64 regs (live only after prologue)
    #pragma unroll
    for (int mt = 0; mt < 4; mt++)
        #pragma unroll
        for (int nt = 0; nt < 4; nt++)
            #pragma unroll
            for (int i = 0; i < 4; i++) acc[mt][nt][i] = 0.0f;

    __syncthreads();

    // ---- unbroken compute: 16 k-steps, B reg double-buffered ----
    const uint4* bbase = (const uint4*)g_Bf16 + (warp_n * 16 * 32 + lane) * 2;
    uint4 qa[2], qb[2];
    {
        qa[0] = bbase[0]; qa[1] = bbase[1];
    }
    #pragma unroll
    for (int ks = 0; ks < 16; ks++) {
        const uint4* cur = (ks & 1) ? qb : qa;
        uint4* nxt = (ks & 1) ? qa : qb;
        if (ks < 15) {
            const uint4* bp = bbase + (size_t)(ks + 1) * 32 * 2;
            nxt[0] = bp[0]; nxt[1] = bp[1];
        }
        uint32_t bf[4][2] = {
            {cur[0].x, cur[0].y}, {cur[0].z, cur[0].w},
            {cur[1].x, cur[1].y}, {cur[1].z, cur[1].w}};
        const uint32_t aoff = (uint32_t)((ks >> 2) * ACHUNK_BYTES + (ks & 3) * 32);
        #pragma unroll
        for (int mt = 0; mt < 4; mt++) {
            uint32_t a0, a1, a2, a3;
            ldsm4(a0, a1, a2, a3, (lm[mt] + aoff) ^ xmask);
            #pragma unroll
            for (int nt = 0; nt < 4; nt++)
                mma16(acc[mt][nt], a0, a1, a2, a3, bf[nt][0], bf[nt][1]);
        }
    }

    // ---- Epilogue (R13-proven): +bias, streaming float2 stores ----
    #pragma unroll
    for (int mt = 0; mt < 4; mt++) {
        const int row0 = block_m + warp_m * 64 + mt * 16 + g;
        #pragma unroll
        for (int nt = 0; nt < 4; nt++) {
            const int col = warp_n * 32 + nt * 8 + t * 2;
            float2 bv = *(const float2*)(bias_s + col);
            float2 v0, v1;
            v0.x = acc[mt][nt][0] + bv.x;
            v0.y = acc[mt][nt][1] + bv.y;
            v1.x = acc[mt][nt][2] + bv.x;
            v1.y = acc[mt][nt][3] + bv.y;
            __stcs((float2*)(out + (size_t)row0 * 128 + col), v0);
            __stcs((float2*)(out + (size_t)(row0 + 8) * 128 + col), v1);
        }
    }
}

extern "C" void kernel_launch(void* const* d_in, const int* in_sizes, int n_in,
                              void* d_out, int out_size) {
    const float* H     = (const float*)d_in[0];
    const float* E     = (const float*)d_in[1];
    const int*   heads = (const int*)d_in[2];
    // d_in[3] = queries (unused)
    const float* W     = (const float*)d_in[4];
    const float* b     = (const float*)d_in[5];
    float* out = (float*)d_out;

    cudaFuncSetAttribute(msg_mma_kernel,
                         cudaFuncAttributeMaxDynamicSharedMemorySize, SMEM_BYTES);

    prep_b16<<<64, 256>>>(W);
    msg_mma_kernel<<<NBLOCKS, 256, SMEM_BYTES>>>(H, E, heads, b, out);
}

// round 17
// speedup vs baseline: 1.2154x; 1.0483x over previous
#include <cuda_runtime.h>
#include <cuda_fp16.h>
#include <cstdint>

#define NBLOCKS 6250
#define ACHUNK_BYTES (128 * 128)            // 128 rows x 64 fp16 cols
#define SMEM_BYTES (4 * ACHUNK_BYTES + 1024)

// fp16 B fragments for mma.m16n8k16, DENSE-LANE layout (4 wf per LDG.128):
// block (wn4, ks) = 64 uint4: [h=0: lanes 0..31][h=1: lanes 0..31].
// uint32 element ((wn4*16+ks)*64 + h*32 + lane)*4 + q holds, with
// nt = h*2 + (q>>1), j = q&1, lane=(g,t):
//   half2( W[wn4*32+nt*8+g][ks*16+2t+8j], W[...][...+1] )
__device__ uint32_t g_Bf16[16384];          // 64 KB, L1/L2-resident

__global__ void prep_b16(const float* __restrict__ W) {
    int i = blockIdx.x * 256 + threadIdx.x;   // 0..16383
    int wn4  = i >> 12;          // 0..3
    int ks   = (i >> 8) & 15;    // 0..15
    int h    = (i >> 7) & 1;
    int lane = (i >> 2) & 31;
    int q    = i & 3;
    int nt = h * 2 + (q >> 1), j = q & 1;
    int g = lane >> 2, t = lane & 3;
    int n = wn4 * 32 + nt * 8 + g;            // UNpermuted col map (R13-proven)
    int k = ks * 16 + 2 * t + 8 * j;
    __half2 hv = __floats2half2_rn(W[n * 256 + k], W[n * 256 + k + 1]);
    g_Bf16[i] = *(uint32_t*)&hv;
}

__device__ __forceinline__ uint32_t smem_u32(const void* p) {
    uint32_t a;
    asm("{ .reg .u64 t; cvta.to.shared.u64 t, %1; cvt.u32.u64 %0, t; }" : "=r"(a) : "l"(p));
    return a;
}
__device__ __forceinline__ uint32_t pack_h2(float x, float y) {
    __half2 h = __floats2half2_rn(x, y);
    return *(uint32_t*)&h;
}
__device__ __forceinline__ void ldsm4(uint32_t& a0, uint32_t& a1, uint32_t& a2,
                                      uint32_t& a3, uint32_t addr) {
    asm volatile("ldmatrix.sync.aligned.m8n8.x4.shared.b16 {%0,%1,%2,%3}, [%4];"
                 : "=r"(a0), "=r"(a1), "=r"(a2), "=r"(a3) : "r"(addr));
}
__device__ __forceinline__ void mma16(float* acc, uint32_t a0, uint32_t a1,
                                      uint32_t a2, uint32_t a3,
                                      uint32_t b0, uint32_t b1) {
    asm volatile(
        "mma.sync.aligned.m16n8k16.row.col.f32.f16.f16.f32 "
        "{%0,%1,%2,%3}, {%4,%5,%6,%7}, {%8,%9}, {%0,%1,%2,%3};\n"
        : "+f"(acc[0]), "+f"(acc[1]), "+f"(acc[2]), "+f"(acc[3])
        : "r"(a0), "r"(a1), "r"(a2), "r"(a3), "r"(b0), "r"(b1));
}

// CTA: 128 edges x 128 outputs. 256 threads = 8 warps (2M x 4N), warp tile 64x32.
// Wide prologue (R16-proven): 4 staging sets, all LDGs in flight, one barrier,
// unbroken 16-kstep mma stream. B via DENSE-LANE LDG.128 (4 wf/op).
__global__ void __launch_bounds__(256, 2) msg_mma_kernel(
    const float* __restrict__ H,
    const float* __restrict__ E,
    const int*   __restrict__ heads,
    const float* __restrict__ bias,
    float*       __restrict__ out)
{
    extern __shared__ __align__(1024) char smem[];
    float* bias_s  = (float*)(smem + 4 * ACHUNK_BYTES);
    int*   heads_s = (int*)(bias_s + 128);
    const uint32_t sbase = smem_u32(smem);

    const int tid  = threadIdx.x;
    const int warp = tid >> 5;
    const int lane = tid & 31;
    const int warp_m = warp >> 2;        // 0..1 -> rows warp_m*64
    const int warp_n = warp & 3;         // 0..3 -> cols warp_n*32
    const int g = lane >> 2;
    const int t = lane & 3;
    const int block_m = blockIdx.x * 128;

    if (tid < 128) {
        bias_s[tid]  = bias[tid];
        heads_s[tid] = heads[block_m + tid];
    }
    __syncthreads();

    // ---- A-load lane mapping: 16 lanes cover one row's 64-float chunk ----
    const int lane_lo = lane & 15;
    const int half    = lane >> 4;
    const int rbase   = warp * 16 + half;   // rows rbase + 2*o, o = 0..7

    // ---- WIDE PROLOGUE: 4 independent staging sets, all LDGs in flight ----
    uint2 stg0[8], stg1[8], stg2[8], stg3[8];
    {
        uint2* sets[4] = {stg0, stg1, stg2, stg3};
        #pragma unroll
        for (int c = 0; c < 4; c++) {
            const int coff = (c & 1) * 64 + lane_lo * 4;
            uint2* sg = sets[c];
            #pragma unroll
            for (int o = 0; o < 8; o++) {
                const int row = rbase + o * 2;
                float4 v;
                if (c < 2) {
                    v = *(const float4*)(H + (size_t)heads_s[row] * 128 + coff);
                } else {
                    v = __ldcs((const float4*)(E + (size_t)(block_m + row) * 128 + coff));
                }
                sg[o] = make_uint2(pack_h2(v.x, v.y), pack_h2(v.z, v.w));
            }
        }
        #pragma unroll
        for (int c = 0; c < 4; c++) {
            const uint32_t off = (uint32_t)(c * ACHUNK_BYTES);
            uint2* sg = sets[c];
            #pragma unroll
            for (int o = 0; o < 8; o++) {
                const int row = rbase + o * 2;
                uint32_t b = (uint32_t)(row * 128 + lane_lo * 8);
                b ^= (uint32_t)((row & 7) << 4);
                *(uint2*)(smem + off + b) = sg[o];
            }
        }
    }

    // ---- ldmatrix lane bases per mt: UNSWIZZLED; XOR mask applied at use ----
    const int row_sel = (lane & 7) + ((lane >> 3) & 1) * 8;
    const int kb2     = ((lane >> 4) & 1) * 16;
    const uint32_t xmask = (uint32_t)((lane & 7) << 4);
    uint32_t lm[4];
    #pragma unroll
    for (int mt = 0; mt < 4; mt++) {
        const int row0 = warp_m * 64 + mt * 16;
        lm[mt] = sbase + (uint32_t)((row0 + row_sel) * 128 + kb2);
    }

    float acc[4][4][4];                     // 64 regs (live only after prologue)
    #pragma unroll
    for (int mt = 0; mt < 4; mt++)
        #pragma unroll
        for (int nt = 0; nt < 4; nt++)
            #pragma unroll
            for (int i = 0; i < 4; i++) acc[mt][nt][i] = 0.0f;

    __syncthreads();

    // ---- unbroken compute: 16 k-steps, B reg double-buffered, DENSE LDG ----
    const uint4* bbase = (const uint4*)g_Bf16 + warp_n * 16 * 64 + lane;
    uint4 qa[2], qb[2];
    {
        qa[0] = bbase[0]; qa[1] = bbase[32];
    }
    #pragma unroll
    for (int ks = 0; ks < 16; ks++) {
        const uint4* cur = (ks & 1) ? qb : qa;
        uint4* nxt = (ks & 1) ? qa : qb;
        if (ks < 15) {
            const uint4* bp = bbase + (ks + 1) * 64;
            nxt[0] = bp[0]; nxt[1] = bp[32];
        }
        uint32_t bf[4][2] = {
            {cur[0].x, cur[0].y}, {cur[0].z, cur[0].w},
            {cur[1].x, cur[1].y}, {cur[1].z, cur[1].w}};
        const uint32_t aoff = (uint32_t)((ks >> 2) * ACHUNK_BYTES + (ks & 3) * 32);
        #pragma unroll
        for (int mt = 0; mt < 4; mt++) {
            uint32_t a0, a1, a2, a3;
            ldsm4(a0, a1, a2, a3, (lm[mt] + aoff) ^ xmask);
            #pragma unroll
            for (int nt = 0; nt < 4; nt++)
                mma16(acc[mt][nt], a0, a1, a2, a3, bf[nt][0], bf[nt][1]);
        }
    }

    // ---- Epilogue (R13/R16-proven): +bias, streaming float2 stores ----
    #pragma unroll
    for (int mt = 0; mt < 4; mt++) {
        const int row0 = block_m + warp_m * 64 + mt * 16 + g;
        #pragma unroll
        for (int nt = 0; nt < 4; nt++) {
            const int col = warp_n * 32 + nt * 8 + t * 2;
            float2 bv = *(const float2*)(bias_s + col);
            float2 v0, v1;
            v0.x = acc[mt][nt][0] + bv.x;
            v0.y = acc[mt][nt][1] + bv.y;
            v1.x = acc[mt][nt][2] + bv.x;
            v1.y = acc[mt][nt][3] + bv.y;
            __stcs((float2*)(out + (size_t)row0 * 128 + col), v0);
            __stcs((float2*)(out + (size_t)(row0 + 8) * 128 + col), v1);
        }
    }
}

extern "C" void kernel_launch(void* const* d_in, const int* in_sizes, int n_in,
                              void* d_out, int out_size) {
    const float* H     = (const float*)d_in[0];
    const float* E     = (const float*)d_in[1];
    const int*   heads = (const int*)d_in[2];
    // d_in[3] = queries (unused)
    const float* W     = (const float*)d_in[4];
    const float* b     = (const float*)d_in[5];
    float* out = (float*)d_out;

    cudaFuncSetAttribute(msg_mma_kernel,
                         cudaFuncAttributeMaxDynamicSharedMemorySize, SMEM_BYTES);

    prep_b16<<<64, 256>>>(W);
    msg_mma_kernel<<<NBLOCKS, 256, SMEM_BYTES>>>(H, E, heads, b, out);
}